// round 15
// baseline (speedup 1.0000x reference)
#include <cuda_runtime.h>

#define TT 2048
#define MM 64
#define HH 256
#define DINN 256
#define DOUTT 256
#define MH (MM*HH)
#define NCTA 128           // 2 CTAs per module
#define SROWS 200          // weight k-rows in SMEM per matrix (x2 = 204.8KB)
#define RROWS 56           // weight k-rows in registers per matrix
#define CHUNK 128          // steps per launch -> 16 launches
#define MAXDEP 132

// ---------------- device scratch ----------------
__device__ float    g_X[TT * HH];
__device__ float    g_Hh[(TT + 1) * MH];
__device__ int      g_act[MM * MM];
__device__ int      g_nact[MM];
__device__ int      g_inm[MM];
__device__ int      g_dep[MM * MAXDEP];     // dependency CTA ids per module
__device__ int      g_ndep[MM];
__device__ unsigned g_flags[NCTA];          // per-CTA monotonic completed-step counter

// ---------------- XLA:GPU EmitTanh (bit-exact, verified R12-R14) -----------
__device__ __forceinline__ float tanh_ref(float x) {
    const float kClamp = 7.99881172180175781f;
    float xc = fminf(fmaxf(x, -kClamp), kClamp);
    float x2 = __fmul_rn(xc, xc);
    float p = -2.76076847742355e-16f;
    p = fmaf(p, x2,  2.00018790482477e-13f);
    p = fmaf(p, x2, -8.60467152213735e-11f);
    p = fmaf(p, x2,  5.12229709037114e-08f);
    p = fmaf(p, x2,  1.48572235717979e-05f);
    p = fmaf(p, x2,  6.37261928875436e-04f);
    p = fmaf(p, x2,  4.89352455891786e-03f);
    p = __fmul_rn(xc, p);
    float q = 1.19825839466702e-06f;
    q = fmaf(q, x2,  1.18534705686654e-04f);
    q = fmaf(q, x2,  2.26843463243900e-03f);
    q = fmaf(q, x2,  4.89352518554385e-03f);
    float r = __fdiv_rn(p, q);
    r = (fabsf(x) < 0.0004f) ? x : r;
    return (fabsf(x) < 20.0f) ? r : copysignf(1.0f, x);
}

// ---------------- init (every replay) ------------------------------------
__global__ void k_init() {
    int i = blockIdx.x * blockDim.x + threadIdx.x;
    if (i < MH) g_Hh[i] = 0.0f;
    if (i < NCTA) g_flags[i] = 0u;
}

__global__ void k_setup(const int* __restrict__ conn, const int* __restrict__ in_conn) {
    int m = threadIdx.x;          // 64 threads
    int n = 0;
    bool self_in = false;
    for (int i = 0; i < MM; i++)
        if (conn[i * MM + m]) {
            g_act[m * MM + n] = i;                 // ascending i
            if (i == m) self_in = true;
            n++;
        }
    g_nact[m] = n;
    g_inm[m]  = in_conn[m];
    // dependency CTA list: both CTAs of every act module, plus self pair
    int nd = 0;
    for (int a = 0; a < n; a++) {
        int i = g_act[m * MM + a];
        g_dep[m * MAXDEP + nd++] = 2 * i;
        g_dep[m * MAXDEP + nd++] = 2 * i + 1;
    }
    if (!self_in) {
        g_dep[m * MAXDEP + nd++] = 2 * m;
        g_dep[m * MAXDEP + nd++] = 2 * m + 1;
    }
    g_ndep[m] = nd;
}

// ---------------- X = x_seq @ in_proj (bit-exact path; unchanged) --------
__global__ void k_inproj(const float* __restrict__ x, const float* __restrict__ P) {
    __shared__ float xs[8][DINN];
    int t0 = blockIdx.x * 8;
    int c  = threadIdx.x;
    #pragma unroll
    for (int j = 0; j < 8; j++) xs[j][c] = x[(size_t)(t0 + j) * DINN + c];
    __syncthreads();
    float acc[8] = {0, 0, 0, 0, 0, 0, 0, 0};
    for (int k = 0; k < DINN; k++) {
        float p = __ldg(&P[(size_t)k * HH + c]);
        #pragma unroll
        for (int j = 0; j < 8; j++) acc[j] = fmaf(xs[j][k], p, acc[j]);
    }
    #pragma unroll
    for (int j = 0; j < 8; j++) g_X[(size_t)(t0 + j) * HH + c] = acc[j];
}

// ---------------- CHUNK fused RNN steps, dataflow-synchronized ------------
// 128 CTAs: module m = bid>>1, column half obase = (bid&1)*128.
// 128 threads: tid 0..63 Wx chains (2 cols), tid 64..127 Wh chains (2 cols).
// No global barrier: per-CTA monotonic flags; each CTA waits only on the
// producers it reads (history buffer makes run-ahead safe).
__global__ void __launch_bounds__(128, 1)
k_chunk(const float* __restrict__ Wx, const float* __restrict__ Wh,
        const float* __restrict__ b, int t0)
{
    extern __shared__ float s_w[];     // [2][SROWS][128] slice-local weights
    __shared__ __align__(16) float inp_s[HH];
    __shared__ __align__(16) float hp_s[HH];
    __shared__ __align__(16) float red_s[128];
    __shared__ int act[MM];
    __shared__ int dep_s[MAXDEP];

    const int bid   = blockIdx.x;
    const int m     = bid >> 1;
    const int obase = (bid & 1) * 128;
    const int tid   = threadIdx.x;
    const int wsel  = tid >> 6;              // 0: Wx, 1: Wh
    const int cc    = (tid & 63) * 2;        // slice-local col pair
    const float* WxM = Wx + (size_t)m * HH * HH;
    const float* WhM = Wh + (size_t)m * HH * HH;

    // ---- stage SMEM weight slices (rows [0,SROWS) of both matrices) ----
    for (int i = tid; i < SROWS * 32; i += 128) {       // float4 units
        int k  = i >> 5;
        int c4 = (i & 31) << 2;
        *(float4*)(s_w + (size_t)k * 128 + c4) =
            *(const float4*)(WxM + (size_t)k * HH + obase + c4);
        *(float4*)(s_w + (size_t)SROWS * 128 + (size_t)k * 128 + c4) =
            *(const float4*)(WhM + (size_t)k * HH + obase + c4);
    }
    // ---- stage register weight rows [SROWS,256) for this thread's matrix ----
    float2 wr[RROWS];
    {
        const float* Wm = wsel ? WhM : WxM;
        #pragma unroll
        for (int j = 0; j < RROWS; j++)
            wr[j] = *(const float2*)(Wm + (size_t)(SROWS + j) * HH + obase + cc);
    }
    const int n_act = g_nact[m];
    const int ndep  = g_ndep[m];
    if (tid < MM) act[tid] = g_act[m * MM + tid];
    for (int j = tid; j < ndep; j += 128) dep_s[j] = g_dep[m * MAXDEP + j];
    const int inm = g_inm[m];
    float b0 = 0.f, b1 = 0.f;
    if (wsel) { b0 = b[(size_t)m * HH + obase + cc];
                b1 = b[(size_t)m * HH + obase + cc + 1]; }
    const float* vsrc = wsel ? hp_s : inp_s;
    const float* wsm  = s_w + (wsel ? (size_t)SROWS * 128 : 0);
    __syncthreads();

    for (int s = 0; s < CHUNK; s++) {
        const int t = t0 + s;
        const float* hc = g_Hh + (size_t)t * MH;

        // ---- dataflow wait: producers of h_t must have completed step t-1 ----
        if (t > 0) {
            for (int j = tid; j < ndep; j += 128) {
                volatile unsigned* f = &g_flags[dep_s[j]];
                while (*f < (unsigned)t) { }
            }
            __threadfence();      // acquire: order flag reads before h loads
        }
        __syncthreads();

        // ---- phase A: inp = rec + ext (per-element order identical R12/R13) ----
        {
            const int k2 = 2 * tid;
            float r0 = 0.f, r1 = 0.f;
            #pragma unroll 8
            for (int a = 0; a < n_act; a++) {
                float2 hv = __ldcg((const float2*)(hc + act[a] * HH + k2));
                r0 += hv.x;
                r1 += hv.y;
            }
            float e0 = inm ? g_X[(size_t)t * HH + k2]     : 0.0f;
            float e1 = inm ? g_X[(size_t)t * HH + k2 + 1] : 0.0f;
            inp_s[k2]     = __fadd_rn(r0, e0);
            inp_s[k2 + 1] = __fadd_rn(r1, e1);
            float2 hp = __ldcg((const float2*)(hc + (size_t)m * HH + k2));
            hp_s[k2]     = hp.x;
            hp_s[k2 + 1] = hp.y;
        }
        __syncthreads();

        // ---- phase B: ascending-k single-accumulator fmaf chains (2 cols) ----
        float a0 = 0.f, a1 = 0.f;
        #pragma unroll 8
        for (int k = 0; k < SROWS; k++) {
            float sv = vsrc[k];
            float2 w = *(const float2*)(wsm + (size_t)k * 128 + cc);
            a0 = fmaf(sv, w.x, a0);
            a1 = fmaf(sv, w.y, a1);
        }
        #pragma unroll
        for (int j = 0; j < RROWS; j++) {
            float sv = vsrc[SROWS + j];
            a0 = fmaf(sv, wr[j].x, a0);
            a1 = fmaf(sv, wr[j].y, a1);
        }
        if (!wsel) { red_s[cc] = a0; red_s[cc + 1] = a1; }
        __syncthreads();

        // ---- combine (e1 + e2) + b, tanh, store (Wh threads) ----
        if (wsel) {
            float r0 = __fadd_rn(__fadd_rn(red_s[cc],     a0), b0);
            float r1 = __fadd_rn(__fadd_rn(red_s[cc + 1], a1), b1);
            float2 hv = make_float2(tanh_ref(r0), tanh_ref(r1));
            __stcg((float2*)(g_Hh + (size_t)(t + 1) * MH + (size_t)m * HH + obase + cc), hv);
            __threadfence();      // release: h stores visible before flag
        }
        __syncthreads();

        // ---- publish completion (monotonic; valid across chunk launches) ----
        if (tid == 0)
            *((volatile unsigned*)&g_flags[bid]) = (unsigned)(t + 1);
        __syncthreads();
    }
}

// ---------------- outputs[t] (not fed back; unchanged) -------------------
__global__ void k_outproj(const float* __restrict__ P, const int* __restrict__ out_conn,
                          float* __restrict__ out)
{
    __shared__ float Ss[8][HH];
    __shared__ int oact[MM];
    __shared__ int n_o_s;
    int t0 = blockIdx.x * 8;
    int c  = threadIdx.x;
    if (c == 0) {
        int n = 0;
        for (int i = 0; i < MM; i++) if (out_conn[i]) oact[n++] = i;
        n_o_s = n;
    }
    __syncthreads();
    const int n_o = n_o_s;
    for (int j = 0; j < 8; j++) {
        const float* hr = g_Hh + (size_t)(t0 + j + 1) * MH;
        float s = 0.0f;
        for (int a = 0; a < n_o; a++) s += hr[oact[a] * HH + c];
        Ss[j][c] = s;
    }
    __syncthreads();
    float acc[8] = {0, 0, 0, 0, 0, 0, 0, 0};
    for (int k = 0; k < HH; k++) {
        float p = __ldg(&P[(size_t)k * DOUTT + c]);
        #pragma unroll
        for (int j = 0; j < 8; j++) acc[j] = fmaf(Ss[j][k], p, acc[j]);
    }
    #pragma unroll
    for (int j = 0; j < 8; j++) out[(size_t)(t0 + j) * DOUTT + c] = acc[j];
}

__global__ void k_hfinal(float* __restrict__ out) {
    int i = blockIdx.x * blockDim.x + threadIdx.x;
    out[(size_t)TT * DOUTT + i] = g_Hh[(size_t)TT * MH + i];
}

// ---------------- launch ---------------------------------------------------
extern "C" void kernel_launch(void* const* d_in, const int* in_sizes, int n_in,
                              void* d_out, int out_size) {
    const float *x = 0, *Wx = 0, *Wh = 0, *b = 0, *inP = 0, *outP = 0;
    const int *conn = 0, *in_conn = 0, *out_conn = 0;

    bool alpha = (n_in >= 2 && in_sizes[0] == MM * HH * HH && in_sizes[1] == MM * HH * HH);
    int nW = 0, nP = 0, nC = 0;
    for (int i = 0; i < n_in; i++) {
        int s = in_sizes[i];
        if (s == TT * DINN)           x = (const float*)d_in[i];
        else if (s == MM * HH * HH) {
            if (nW == 0) { if (alpha) Wh = (const float*)d_in[i]; else Wx = (const float*)d_in[i]; }
            else         { if (alpha) Wx = (const float*)d_in[i]; else Wh = (const float*)d_in[i]; }
            nW++;
        }
        else if (s == MM * HH)        b = (const float*)d_in[i];
        else if (s == DINN * HH) {
            if (nP == 0) inP = (const float*)d_in[i]; else outP = (const float*)d_in[i];
            nP++;
        }
        else if (s == MM * MM)        conn = (const int*)d_in[i];
        else if (s == MM) {
            if (nC == 0) in_conn = (const int*)d_in[i]; else out_conn = (const int*)d_in[i];
            nC++;
        }
    }
    float* out = (float*)d_out;

    const int dyn = 2 * SROWS * 128 * (int)sizeof(float);   // 204,800 B
    cudaFuncSetAttribute((const void*)k_chunk,
                         cudaFuncAttributeMaxDynamicSharedMemorySize, dyn);

    k_init  <<<64, 256>>>();
    k_setup <<<1, 64>>>(conn, in_conn);
    k_inproj<<<TT / 8, 256>>>(x, inP);
    for (int t0 = 0; t0 < TT; t0 += CHUNK)
        k_chunk<<<NCTA, 128, dyn>>>(Wx, Wh, b, t0);
    k_outproj<<<TT / 8, 256>>>(outP, out_conn, out);
    if (out_size >= TT * DOUTT + MM * HH)
        k_hfinal<<<MH / 256, 256>>>(out);
}

// round 16
// speedup vs baseline: 1.4817x; 1.4817x over previous
#include <cuda_runtime.h>

#define TT 2048
#define MM 64
#define HH 256
#define DINN 256
#define DOUTT 256
#define MH (MM*HH)
#define NCTA 128           // 2 CTAs per module
#define SROWS 200          // weight k-rows in SMEM per matrix (x2 = 204.8KB)
#define RROWS 56           // weight k-rows in registers per matrix
#define CHUNK 128          // steps per launch -> 16 launches

// ---------------- device scratch ----------------
__device__ float    g_X[TT * HH];
__device__ float    g_Hh[(TT + 1) * MH];
__device__ int      g_act[MM * MM];
__device__ int      g_nact[MM];
__device__ int      g_inm[MM];
__device__ __align__(128) unsigned g_arrive;    // arrival counter (own line)
__device__ __align__(128) unsigned g_release;   // release step (own line, read-shared)

// ---------------- XLA:GPU EmitTanh (bit-exact, verified R12-R15) -----------
__device__ __forceinline__ float tanh_ref(float x) {
    const float kClamp = 7.99881172180175781f;
    float xc = fminf(fmaxf(x, -kClamp), kClamp);
    float x2 = __fmul_rn(xc, xc);
    float p = -2.76076847742355e-16f;
    p = fmaf(p, x2,  2.00018790482477e-13f);
    p = fmaf(p, x2, -8.60467152213735e-11f);
    p = fmaf(p, x2,  5.12229709037114e-08f);
    p = fmaf(p, x2,  1.48572235717979e-05f);
    p = fmaf(p, x2,  6.37261928875436e-04f);
    p = fmaf(p, x2,  4.89352455891786e-03f);
    p = __fmul_rn(xc, p);
    float q = 1.19825839466702e-06f;
    q = fmaf(q, x2,  1.18534705686654e-04f);
    q = fmaf(q, x2,  2.26843463243900e-03f);
    q = fmaf(q, x2,  4.89352518554385e-03f);
    float r = __fdiv_rn(p, q);
    r = (fabsf(x) < 0.0004f) ? x : r;
    return (fabsf(x) < 20.0f) ? r : copysignf(1.0f, x);
}

// ---------------- init (every replay) ------------------------------------
__global__ void k_init() {
    int i = blockIdx.x * blockDim.x + threadIdx.x;
    if (i < MH) g_Hh[i] = 0.0f;
    if (i == 0) { g_arrive = 0u; g_release = 0u; }
}

__global__ void k_setup(const int* __restrict__ conn, const int* __restrict__ in_conn) {
    int m = threadIdx.x;
    int n = 0;
    for (int i = 0; i < MM; i++)
        if (conn[i * MM + m]) g_act[m * MM + (n++)] = i;   // ascending i
    g_nact[m] = n;
    g_inm[m]  = in_conn[m];
}

// ---------------- X = x_seq @ in_proj (bit-exact path; unchanged) --------
__global__ void k_inproj(const float* __restrict__ x, const float* __restrict__ P) {
    __shared__ float xs[8][DINN];
    int t0 = blockIdx.x * 8;
    int c  = threadIdx.x;
    #pragma unroll
    for (int j = 0; j < 8; j++) xs[j][c] = x[(size_t)(t0 + j) * DINN + c];
    __syncthreads();
    float acc[8] = {0, 0, 0, 0, 0, 0, 0, 0};
    for (int k = 0; k < DINN; k++) {
        float p = __ldg(&P[(size_t)k * HH + c]);
        #pragma unroll
        for (int j = 0; j < 8; j++) acc[j] = fmaf(xs[j][k], p, acc[j]);
    }
    #pragma unroll
    for (int j = 0; j < 8; j++) g_X[(size_t)(t0 + j) * HH + c] = acc[j];
}

// ---------------- CHUNK fused RNN steps (R13 body + cheap barrier) --------
// 128 CTAs: module m = bid>>1, column half obase = (bid&1)*128.
// 128 threads: tid 0..63 Wx chains (2 cols), tid 64..127 Wh chains (2 cols).
__global__ void __launch_bounds__(128, 1)
k_chunk(const float* __restrict__ Wx, const float* __restrict__ Wh,
        const float* __restrict__ b, int t0)
{
    extern __shared__ float s_w[];     // [2][SROWS][128] slice-local weights
    __shared__ __align__(16) float inp_s[HH];
    __shared__ __align__(16) float hp_s[HH];
    __shared__ __align__(16) float red_s[128];
    __shared__ int act[MM];

    const int bid   = blockIdx.x;
    const int m     = bid >> 1;
    const int obase = (bid & 1) * 128;
    const int tid   = threadIdx.x;
    const int wsel  = tid >> 6;              // 0: Wx, 1: Wh
    const int cc    = (tid & 63) * 2;        // slice-local col pair
    const float* WxM = Wx + (size_t)m * HH * HH;
    const float* WhM = Wh + (size_t)m * HH * HH;

    // ---- stage SMEM weight slices (rows [0,SROWS) of both matrices) ----
    for (int i = tid; i < SROWS * 32; i += 128) {       // float4 units
        int k  = i >> 5;
        int c4 = (i & 31) << 2;
        *(float4*)(s_w + (size_t)k * 128 + c4) =
            *(const float4*)(WxM + (size_t)k * HH + obase + c4);
        *(float4*)(s_w + (size_t)SROWS * 128 + (size_t)k * 128 + c4) =
            *(const float4*)(WhM + (size_t)k * HH + obase + c4);
    }
    // ---- stage register weight rows [SROWS,256) for this thread's matrix ----
    float2 wr[RROWS];
    {
        const float* Wm = wsel ? WhM : WxM;
        #pragma unroll
        for (int j = 0; j < RROWS; j++)
            wr[j] = *(const float2*)(Wm + (size_t)(SROWS + j) * HH + obase + cc);
    }
    if (tid < MM) act[tid] = g_act[m * MM + tid];
    const int n_act = g_nact[m];
    const int inm   = g_inm[m];
    float b0 = 0.f, b1 = 0.f;
    if (wsel) { b0 = b[(size_t)m * HH + obase + cc];
                b1 = b[(size_t)m * HH + obase + cc + 1]; }
    const float* vsrc = wsel ? hp_s : inp_s;
    const float* wsm  = s_w + (wsel ? (size_t)SROWS * 128 : 0);
    __syncthreads();

    for (int s = 0; s < CHUNK; s++) {
        const int t = t0 + s;
        const float* hc = g_Hh + (size_t)t * MH;

        // ---- phase A: inp = rec + ext (per-element order identical R13) ----
        {
            const int k2 = 2 * tid;
            float r0 = 0.f, r1 = 0.f;
            #pragma unroll 8
            for (int a = 0; a < n_act; a++) {
                float2 hv = __ldcg((const float2*)(hc + act[a] * HH + k2));
                r0 += hv.x;
                r1 += hv.y;
            }
            float e0 = inm ? g_X[(size_t)t * HH + k2]     : 0.0f;
            float e1 = inm ? g_X[(size_t)t * HH + k2 + 1] : 0.0f;
            inp_s[k2]     = __fadd_rn(r0, e0);
            inp_s[k2 + 1] = __fadd_rn(r1, e1);
            float2 hp = __ldcg((const float2*)(hc + (size_t)m * HH + k2));
            hp_s[k2]     = hp.x;
            hp_s[k2 + 1] = hp.y;
        }
        __syncthreads();

        // ---- phase B: ascending-k single-accumulator fmaf chains (2 cols) ----
        float a0 = 0.f, a1 = 0.f;
        #pragma unroll 8
        for (int k = 0; k < SROWS; k++) {
            float sv = vsrc[k];
            float2 w = *(const float2*)(wsm + (size_t)k * 128 + cc);
            a0 = fmaf(sv, w.x, a0);
            a1 = fmaf(sv, w.y, a1);
        }
        #pragma unroll
        for (int j = 0; j < RROWS; j++) {
            float sv = vsrc[SROWS + j];
            a0 = fmaf(sv, wr[j].x, a0);
            a1 = fmaf(sv, wr[j].y, a1);
        }
        if (!wsel) { red_s[cc] = a0; red_s[cc + 1] = a1; }
        __syncthreads();

        // ---- combine (e1 + e2) + b, tanh, store (Wh threads) ----
        if (wsel) {
            float r0 = __fadd_rn(__fadd_rn(red_s[cc],     a0), b0);
            float r1 = __fadd_rn(__fadd_rn(red_s[cc + 1], a1), b1);
            float2 hv = make_float2(tanh_ref(r0), tanh_ref(r1));
            __stcg((float2*)(g_Hh + (size_t)(t + 1) * MH + (size_t)m * HH + obase + cc), hv);
        }
        __syncthreads();     // all h stores issued (CTA-wide) before tid0 fences

        // ---- grid barrier: ONE fence + ONE atomic per CTA; split lines ----
        if (tid == 0) {
            __threadfence();                          // publish CTA's h stores
            unsigned old = atomicAdd(&g_arrive, 1u);  // arrival (uncontended line)
            const unsigned target = (unsigned)(t + 1) * NCTA;
            if (old == target - 1u) {
                __threadfence();
                *((volatile unsigned*)&g_release) = (unsigned)(t + 1);
            }
            if (s < CHUNK - 1) {
                volatile unsigned* r = &g_release;    // read-shared line
                while (*r < (unsigned)(t + 1)) { }
                __threadfence();                      // acquire
            }
        }
        __syncthreads();
    }
}

// ---------------- outputs[t] (not fed back; unchanged) -------------------
__global__ void k_outproj(const float* __restrict__ P, const int* __restrict__ out_conn,
                          float* __restrict__ out)
{
    __shared__ float Ss[8][HH];
    __shared__ int oact[MM];
    __shared__ int n_o_s;
    int t0 = blockIdx.x * 8;
    int c  = threadIdx.x;
    if (c == 0) {
        int n = 0;
        for (int i = 0; i < MM; i++) if (out_conn[i]) oact[n++] = i;
        n_o_s = n;
    }
    __syncthreads();
    const int n_o = n_o_s;
    for (int j = 0; j < 8; j++) {
        const float* hr = g_Hh + (size_t)(t0 + j + 1) * MH;
        float s = 0.0f;
        for (int a = 0; a < n_o; a++) s += hr[oact[a] * HH + c];
        Ss[j][c] = s;
    }
    __syncthreads();
    float acc[8] = {0, 0, 0, 0, 0, 0, 0, 0};
    for (int k = 0; k < HH; k++) {
        float p = __ldg(&P[(size_t)k * DOUTT + c]);
        #pragma unroll
        for (int j = 0; j < 8; j++) acc[j] = fmaf(Ss[j][k], p, acc[j]);
    }
    #pragma unroll
    for (int j = 0; j < 8; j++) out[(size_t)(t0 + j) * DOUTT + c] = acc[j];
}

__global__ void k_hfinal(float* __restrict__ out) {
    int i = blockIdx.x * blockDim.x + threadIdx.x;
    out[(size_t)TT * DOUTT + i] = g_Hh[(size_t)TT * MH + i];
}

// ---------------- launch ---------------------------------------------------
extern "C" void kernel_launch(void* const* d_in, const int* in_sizes, int n_in,
                              void* d_out, int out_size) {
    const float *x = 0, *Wx = 0, *Wh = 0, *b = 0, *inP = 0, *outP = 0;
    const int *conn = 0, *in_conn = 0, *out_conn = 0;

    bool alpha = (n_in >= 2 && in_sizes[0] == MM * HH * HH && in_sizes[1] == MM * HH * HH);
    int nW = 0, nP = 0, nC = 0;
    for (int i = 0; i < n_in; i++) {
        int s = in_sizes[i];
        if (s == TT * DINN)           x = (const float*)d_in[i];
        else if (s == MM * HH * HH) {
            if (nW == 0) { if (alpha) Wh = (const float*)d_in[i]; else Wx = (const float*)d_in[i]; }
            else         { if (alpha) Wx = (const float*)d_in[i]; else Wh = (const float*)d_in[i]; }
            nW++;
        }
        else if (s == MM * HH)        b = (const float*)d_in[i];
        else if (s == DINN * HH) {
            if (nP == 0) inP = (const float*)d_in[i]; else outP = (const float*)d_in[i];
            nP++;
        }
        else if (s == MM * MM)        conn = (const int*)d_in[i];
        else if (s == MM) {
            if (nC == 0) in_conn = (const int*)d_in[i]; else out_conn = (const int*)d_in[i];
            nC++;
        }
    }
    float* out = (float*)d_out;

    const int dyn = 2 * SROWS * 128 * (int)sizeof(float);   // 204,800 B
    cudaFuncSetAttribute((const void*)k_chunk,
                         cudaFuncAttributeMaxDynamicSharedMemorySize, dyn);

    k_init  <<<64, 256>>>();
    k_setup <<<1, 64>>>(conn, in_conn);
    k_inproj<<<TT / 8, 256>>>(x, inP);
    for (int t0 = 0; t0 < TT; t0 += CHUNK)
        k_chunk<<<NCTA, 128, dyn>>>(Wx, Wh, b, t0);
    k_outproj<<<TT / 8, 256>>>(outP, out_conn, out);
    if (out_size >= TT * DOUTT + MM * HH)
        k_hfinal<<<MH / 256, 256>>>(out);
}

// round 17
// speedup vs baseline: 1.7688x; 1.1937x over previous
#include <cuda_runtime.h>

#define TT 2048
#define MM 64
#define HH 256
#define DINN 256
#define DOUTT 256
#define MH (MM*HH)
#define NCTA 128           // 2 CTAs per module
#define THREADS 256        // 128 Wx chains + 128 Wh chains (1 col each)
#define SREG 96            // weight k-rows in SMEM per matrix (98.3KB dynamic)
#define RREG 160           // weight k-rows in registers per thread

// ---------------- device scratch ----------------
__device__ float    g_X[TT * HH];
__device__ float    g_Hh[(TT + 1) * MH];
__device__ int      g_act[MM * MM];
__device__ int      g_nact[MM];
__device__ int      g_inm[MM];
__device__ unsigned g_cnt;          // monotonic barrier counter (arrive == release)

// ---------------- XLA:GPU EmitTanh (bit-exact, verified R12-R16) -----------
__device__ __forceinline__ float tanh_ref(float x) {
    const float kClamp = 7.99881172180175781f;
    float xc = fminf(fmaxf(x, -kClamp), kClamp);
    float x2 = __fmul_rn(xc, xc);
    float p = -2.76076847742355e-16f;
    p = fmaf(p, x2,  2.00018790482477e-13f);
    p = fmaf(p, x2, -8.60467152213735e-11f);
    p = fmaf(p, x2,  5.12229709037114e-08f);
    p = fmaf(p, x2,  1.48572235717979e-05f);
    p = fmaf(p, x2,  6.37261928875436e-04f);
    p = fmaf(p, x2,  4.89352455891786e-03f);
    p = __fmul_rn(xc, p);
    float q = 1.19825839466702e-06f;
    q = fmaf(q, x2,  1.18534705686654e-04f);
    q = fmaf(q, x2,  2.26843463243900e-03f);
    q = fmaf(q, x2,  4.89352518554385e-03f);
    float r = __fdiv_rn(p, q);
    r = (fabsf(x) < 0.0004f) ? x : r;
    return (fabsf(x) < 20.0f) ? r : copysignf(1.0f, x);
}

// ---------------- init (every replay) ------------------------------------
__global__ void k_init() {
    int i = blockIdx.x * blockDim.x + threadIdx.x;
    if (i < MH) g_Hh[i] = 0.0f;
    if (i == 0) g_cnt = 0u;
}

__global__ void k_setup(const int* __restrict__ conn, const int* __restrict__ in_conn) {
    int m = threadIdx.x;
    int n = 0;
    for (int i = 0; i < MM; i++)
        if (conn[i * MM + m]) g_act[m * MM + (n++)] = i;   // ascending i
    g_nact[m] = n;
    g_inm[m]  = in_conn[m];
}

// ---------------- X = x_seq @ in_proj (bit-exact path; unchanged) --------
__global__ void k_inproj(const float* __restrict__ x, const float* __restrict__ P) {
    __shared__ float xs[8][DINN];
    int t0 = blockIdx.x * 8;
    int c  = threadIdx.x;
    #pragma unroll
    for (int j = 0; j < 8; j++) xs[j][c] = x[(size_t)(t0 + j) * DINN + c];
    __syncthreads();
    float acc[8] = {0, 0, 0, 0, 0, 0, 0, 0};
    for (int k = 0; k < DINN; k++) {
        float p = __ldg(&P[(size_t)k * HH + c]);
        #pragma unroll
        for (int j = 0; j < 8; j++) acc[j] = fmaf(xs[j][k], p, acc[j]);
    }
    #pragma unroll
    for (int j = 0; j < 8; j++) g_X[(size_t)(t0 + j) * HH + c] = acc[j];
}

// ---------------- persistent fused RNN: all 2048 steps, one launch --------
// 128 CTAs: module m = bid>>1, column half obase = (bid&1)*128.
// 256 threads: tid<128 -> Wx chain col obase+tid; tid>=128 -> Wh chain.
// Weight rows [0,SREG) in SMEM, [SREG,256) in registers.
__global__ void __launch_bounds__(THREADS, 1)
k_chunk(const float* __restrict__ Wx, const float* __restrict__ Wh,
        const float* __restrict__ b)
{
    extern __shared__ float s_w[];     // [2][SREG][128]
    __shared__ __align__(16) float inp_s[HH];
    __shared__ __align__(16) float hp_s[HH];
    __shared__ __align__(16) float red_s[128];
    __shared__ int act[MM];

    const int bid   = blockIdx.x;
    const int m     = bid >> 1;
    const int obase = (bid & 1) * 128;
    const int tid   = threadIdx.x;
    const int half  = tid >> 7;          // 0: Wx chains, 1: Wh chains
    const int c     = tid & 127;         // slice-local column
    const int col   = obase + c;
    const float* WxM = Wx + (size_t)m * HH * HH;
    const float* WhM = Wh + (size_t)m * HH * HH;

    // ---- stage SMEM weight slices: rows [0,SREG) of both matrices ----
    for (int i = tid; i < SREG * 32; i += THREADS) {
        int k  = i >> 5;
        int c4 = (i & 31) << 2;
        *(float4*)(s_w + (size_t)k * 128 + c4) =
            *(const float4*)(WxM + (size_t)k * HH + obase + c4);
        *(float4*)(s_w + (size_t)SREG * 128 + (size_t)k * 128 + c4) =
            *(const float4*)(WhM + (size_t)k * HH + obase + c4);
    }
    // ---- stage register weight rows [SREG,256) for this thread's matrix ----
    float wr[RREG];
    {
        const float* Wm = half ? WhM : WxM;
        #pragma unroll
        for (int j = 0; j < RREG; j++)
            wr[j] = Wm[(size_t)(SREG + j) * HH + col];
    }
    if (tid < MM) act[tid] = g_act[m * MM + tid];
    const int n_act = g_nact[m];
    const int inm   = g_inm[m];
    const float bias = half ? b[(size_t)m * HH + col] : 0.0f;
    const float* vsrc = half ? hp_s : inp_s;
    const float* wsm  = s_w + (half ? (size_t)SREG * 128 : 0);
    __syncthreads();

    #pragma unroll 1
    for (int t = 0; t < TT; t++) {
        const float* hc = g_Hh + (size_t)t * MH;

        // ---- phase A, split by half (R14 body, verified bit-exact) ----
        if (!half) {
            const int k2 = 2 * tid;                // tid 0..127 -> k2 0..254
            float r0 = 0.f, r1 = 0.f;
            #pragma unroll 16
            for (int a = 0; a < n_act; a++) {
                float2 hv = __ldcg((const float2*)(hc + act[a] * HH + k2));
                r0 += hv.x;
                r1 += hv.y;
            }
            float e0 = inm ? g_X[(size_t)t * HH + k2]     : 0.0f;
            float e1 = inm ? g_X[(size_t)t * HH + k2 + 1] : 0.0f;
            inp_s[k2]     = __fadd_rn(r0, e0);
            inp_s[k2 + 1] = __fadd_rn(r1, e1);
            asm volatile("bar.sync 1, 128;" ::: "memory");
        } else {
            const int k2 = 2 * (tid - 128);
            float2 hp = __ldcg((const float2*)(hc + (size_t)m * HH + k2));
            hp_s[k2]     = hp.x;
            hp_s[k2 + 1] = hp.y;
            asm volatile("bar.sync 2, 128;" ::: "memory");
        }

        // ---- chain: ascending-k single-accumulator fmaf (bit-exact) ----
        float a0 = 0.f;
        #pragma unroll
        for (int k4 = 0; k4 < SREG / 4; k4++) {
            float4 v = *(const float4*)(vsrc + 4 * k4);
            a0 = fmaf(v.x, wsm[(size_t)(4 * k4 + 0) * 128 + c], a0);
            a0 = fmaf(v.y, wsm[(size_t)(4 * k4 + 1) * 128 + c], a0);
            a0 = fmaf(v.z, wsm[(size_t)(4 * k4 + 2) * 128 + c], a0);
            a0 = fmaf(v.w, wsm[(size_t)(4 * k4 + 3) * 128 + c], a0);
        }
        #pragma unroll
        for (int j4 = 0; j4 < RREG / 4; j4++) {
            float4 v = *(const float4*)(vsrc + SREG + 4 * j4);
            a0 = fmaf(v.x, wr[4 * j4 + 0], a0);
            a0 = fmaf(v.y, wr[4 * j4 + 1], a0);
            a0 = fmaf(v.z, wr[4 * j4 + 2], a0);
            a0 = fmaf(v.w, wr[4 * j4 + 3], a0);
        }
        if (!half) red_s[c] = a0;
        __syncthreads();

        // ---- combine (e1 + e2) + b, tanh, store (Wh half) ----
        if (half) {
            float r = __fadd_rn(__fadd_rn(red_s[c], a0), bias);
            __stcg(g_Hh + (size_t)(t + 1) * MH + (size_t)m * HH + col, tanh_ref(r));
        }
        __syncthreads();     // CTA-wide: h stores issued before tid0 publishes

        // ---- grid barrier: single monotonic counter (R13), one fence ----
        if (tid == 0) {
            __threadfence();                       // publish this CTA's h stores
            atomicAdd(&g_cnt, 1u);                 // arrival == polled value
            if (t < TT - 1) {
                const unsigned target = (unsigned)(t + 1) * NCTA;
                volatile unsigned* cn = &g_cnt;
                while (*cn < target) { }
                __threadfence();                   // acquire
            }
        }
        __syncthreads();
    }
}

// ---------------- outputs[t] (not fed back; unchanged) -------------------
__global__ void k_outproj(const float* __restrict__ P, const int* __restrict__ out_conn,
                          float* __restrict__ out)
{
    __shared__ float Ss[8][HH];
    __shared__ int oact[MM];
    __shared__ int n_o_s;
    int t0 = blockIdx.x * 8;
    int c  = threadIdx.x;
    if (c == 0) {
        int n = 0;
        for (int i = 0; i < MM; i++) if (out_conn[i]) oact[n++] = i;
        n_o_s = n;
    }
    __syncthreads();
    const int n_o = n_o_s;
    for (int j = 0; j < 8; j++) {
        const float* hr = g_Hh + (size_t)(t0 + j + 1) * MH;
        float s = 0.0f;
        for (int a = 0; a < n_o; a++) s += hr[oact[a] * HH + c];
        Ss[j][c] = s;
    }
    __syncthreads();
    float acc[8] = {0, 0, 0, 0, 0, 0, 0, 0};
    for (int k = 0; k < HH; k++) {
        float p = __ldg(&P[(size_t)k * DOUTT + c]);
        #pragma unroll
        for (int j = 0; j < 8; j++) acc[j] = fmaf(Ss[j][k], p, acc[j]);
    }
    #pragma unroll
    for (int j = 0; j < 8; j++) out[(size_t)(t0 + j) * DOUTT + c] = acc[j];
}

__global__ void k_hfinal(float* __restrict__ out) {
    int i = blockIdx.x * blockDim.x + threadIdx.x;
    out[(size_t)TT * DOUTT + i] = g_Hh[(size_t)TT * MH + i];
}

// ---------------- launch ---------------------------------------------------
extern "C" void kernel_launch(void* const* d_in, const int* in_sizes, int n_in,
                              void* d_out, int out_size) {
    const float *x = 0, *Wx = 0, *Wh = 0, *b = 0, *inP = 0, *outP = 0;
    const int *conn = 0, *in_conn = 0, *out_conn = 0;

    bool alpha = (n_in >= 2 && in_sizes[0] == MM * HH * HH && in_sizes[1] == MM * HH * HH);
    int nW = 0, nP = 0, nC = 0;
    for (int i = 0; i < n_in; i++) {
        int s = in_sizes[i];
        if (s == TT * DINN)           x = (const float*)d_in[i];
        else if (s == MM * HH * HH) {
            if (nW == 0) { if (alpha) Wh = (const float*)d_in[i]; else Wx = (const float*)d_in[i]; }
            else         { if (alpha) Wx = (const float*)d_in[i]; else Wh = (const float*)d_in[i]; }
            nW++;
        }
        else if (s == MM * HH)        b = (const float*)d_in[i];
        else if (s == DINN * HH) {
            if (nP == 0) inP = (const float*)d_in[i]; else outP = (const float*)d_in[i];
            nP++;
        }
        else if (s == MM * MM)        conn = (const int*)d_in[i];
        else if (s == MM) {
            if (nC == 0) in_conn = (const int*)d_in[i]; else out_conn = (const int*)d_in[i];
            nC++;
        }
    }
    float* out = (float*)d_out;

    const int dyn = 2 * SREG * 128 * (int)sizeof(float);   // 98,304 B
    cudaFuncSetAttribute((const void*)k_chunk,
                         cudaFuncAttributeMaxDynamicSharedMemorySize, dyn);

    k_init  <<<64, 256>>>();
    k_setup <<<1, 64>>>(conn, in_conn);
    k_inproj<<<TT / 8, 256>>>(x, inP);
    k_chunk <<<NCTA, THREADS, dyn>>>(Wx, Wh, b);
    k_outproj<<<TT / 8, 256>>>(outP, out_conn, out);
    if (out_size >= TT * DOUTT + MM * HH)
        k_hfinal<<<MH / 256, 256>>>(out);
}